// round 11
// baseline (speedup 1.0000x reference)
#include <cuda_runtime.h>
#include <cuda_fp16.h>
#include <cstdint>
#include <cstddef>

// ---------------- problem constants ----------------
#define MROWS 8192
#define FDIM  1024
#define HDIM  512
#define GDIM  2048
#define KFUSE 1536
#define DSTEPS 8

// ---------------- GEMM tile config ----------------
#define BM 128
#define BN 64
#define BK 64                 // fp16 elems per chunk (128 bytes per row)
#define STAGES 3
#define NTHR 256
#define A_TILE_B (BM*128)     // 16384
#define W_TILE_B (BN*128)     // 8192
#define STAGE_B (A_TILE_B + W_TILE_B)    // 24576
#define SMEM_TOTAL (STAGES*STAGE_B)      // 73728

// ---------------- scratch (device globals) ----------------
__device__ __align__(256) __half g_out[(size_t)MROWS*FDIM];     // x-part of A (cls output)
__device__ __align__(256) __half g_h[2][(size_t)MROWS*HDIM];    // double-buffered h
__device__ __align__(256) __half g_wg[(size_t)GDIM*KFUSE];      // gate-permuted fused W (fp16)
__device__ __align__(256) __half g_wc[(size_t)FDIM*HDIM];       // W_cls (fp16)
__device__ __align__(256) float g_biasg[GDIM];                  // permuted b_ih+b_hh
__device__ __align__(256) float g_c[(size_t)MROWS*HDIM];

// ---------------- helpers ----------------
__device__ __forceinline__ uint32_t smem_u32(const void* p) {
    uint32_t a;
    asm("{ .reg .u64 t; cvta.to.shared.u64 t, %1; cvt.u32.u64 %0, t; }" : "=r"(a) : "l"(p));
    return a;
}
__device__ __forceinline__ void cp16(uint32_t dst, const void* src) {
    asm volatile("cp.async.cg.shared.global [%0], [%1], 16;" :: "r"(dst), "l"(src) : "memory");
}
#define CP_COMMIT() asm volatile("cp.async.commit_group;" ::: "memory")
#define CP_WAIT1()  asm volatile("cp.async.wait_group 1;" ::: "memory")

__device__ __forceinline__ void ldsm4(uint32_t addr, uint32_t& r0, uint32_t& r1, uint32_t& r2, uint32_t& r3) {
    asm volatile("ldmatrix.sync.aligned.m8n8.x4.shared.b16 {%0,%1,%2,%3}, [%4];"
                 : "=r"(r0), "=r"(r1), "=r"(r2), "=r"(r3) : "r"(addr));
}
__device__ __forceinline__ void mma16816(float* c, const uint32_t* a, const uint32_t* b) {
    asm("mma.sync.aligned.m16n8k16.row.col.f32.f16.f16.f32 "
        "{%0,%1,%2,%3}, {%4,%5,%6,%7}, {%8,%9}, {%0,%1,%2,%3};"
        : "+f"(c[0]), "+f"(c[1]), "+f"(c[2]), "+f"(c[3])
        : "r"(a[0]), "r"(a[1]), "r"(a[2]), "r"(a[3]), "r"(b[0]), "r"(b[1]));
}
__device__ __forceinline__ float sigmoidf_(float x) { return 1.0f / (1.0f + __expf(-x)); }

// SW128 swizzle within a 128-row x 128-byte tile: row r (0..127), 16B chunk c (0..7)
__device__ __forceinline__ uint32_t swz128(int r, int c) {
    return (uint32_t)(r * 128 + ((c ^ (r & 7)) << 4));
}

// ---------------- single-pass fp16 HMMA GEMM (+ fused LSTM cell) ----------------
// CTA tile 128x64, 8 warps of 32x32, 3 CTAs/SM. BK=64, 3 stages, 1 sync/chunk.
// A operand per chunk: chunk < xchunks -> Ax (ldax), else Ah (HDIM ld, k rebased).
// mode 0 (gates): gate-permuted output; epilogue applies LSTM cell, updates cstate,
//                 writes h (fp16) into hw [MROWS x HDIM]
// mode 1 (cls):   writes Co (ld DSTEPS*FDIM) and fp16 copy to ox [MROWS x FDIM]
__global__ void __launch_bounds__(NTHR, 3)
gemm_hmma(const __half* __restrict__ Ax, int ldax,
          const __half* __restrict__ Ah, int xchunks,
          const __half* __restrict__ W, int ldw,
          int K,
          const float* __restrict__ bias,
          float* __restrict__ cstate,
          float* __restrict__ Co,
          __half* __restrict__ ox,
          __half* __restrict__ hw,
          int mode, int first)
{
    extern __shared__ char smem[];
    const uint32_t sb = smem_u32(smem);
    const int tid = threadIdx.x;
    const int lane = tid & 31;
    const int wid = tid >> 5;
    const int wm = wid & 3;        // 0..3 -> 32-row slice
    const int wn = wid >> 2;       // 0..1 -> 32-col slice
    const int bm = blockIdx.y, bn = blockIdx.x;
    const int nch = K / BK;

    // loader: granule (row-block, 16B col). r0 in [0,32), c0 in [0,8).
    const int r0g = tid >> 3, c0g = tid & 7;
    const uint32_t dOff = swz128(r0g, c0g);           // +4096 per 32-row block
    const size_t ldxb = (size_t)ldax * 2;
    const size_t ldhb = (size_t)HDIM * 2;
    const size_t ldwb = (size_t)ldw * 2;
    const char* pX = (const char*)Ax + (size_t)(bm * BM + r0g) * ldxb + c0g * 16;
    const char* pH = Ah ? (const char*)Ah + (size_t)(bm * BM + r0g) * ldhb + c0g * 16 : nullptr;
    const char* pW = (const char*)W + (size_t)(bn * BN + r0g) * ldwb + c0g * 16;
    const size_t ldx32 = ldxb * 32, ldh32 = ldhb * 32, ldw32 = ldwb * 32;

    auto load_stage = [&](int slot, int chunk) {
        const uint32_t stg = sb + slot * STAGE_B;
        const bool useH = (chunk >= xchunks);
        const char* a = useH ? pH : pX;
        const size_t lda32 = useH ? ldh32 : ldx32;
        const size_t kba = (size_t)(useH ? (chunk - xchunks) : chunk) * 128;
        const size_t kbw = (size_t)chunk * 128;
#pragma unroll
        for (int k = 0; k < 4; k++)
            cp16(stg + dOff + k * 4096, a + kba + k * lda32);
#pragma unroll
        for (int k = 0; k < 2; k++)
            cp16(stg + A_TILE_B + dOff + k * 4096, pW + kbw + k * ldw32);
    };

    float acc[2][4][4];
#pragma unroll
    for (int mt = 0; mt < 2; mt++)
#pragma unroll
        for (int nt = 0; nt < 4; nt++)
#pragma unroll
            for (int e = 0; e < 4; e++) acc[mt][nt][e] = 0.0f;

    load_stage(0, 0); CP_COMMIT();
    load_stage(1, 1); CP_COMMIT();

    const int lrow = lane & 15;
    const int lchk = lane >> 4;

    // per-thread ldmatrix row constants
    int baseA[2], xA[2], baseW[2], xW[2];
#pragma unroll
    for (int mt = 0; mt < 2; mt++) {
        const int r = wm * 32 + mt * 16 + lrow;
        baseA[mt] = r * 128; xA[mt] = r & 7;
    }
#pragma unroll
    for (int np = 0; np < 2; np++) {
        const int r = wn * 32 + np * 16 + lrow;
        baseW[np] = r * 128; xW[np] = r & 7;
    }

    for (int i = 0; i < nch; i++) {
        CP_WAIT1();
        __syncthreads();
        if (i + 2 < nch) load_stage((i + 2) % STAGES, i + 2);
        CP_COMMIT();

        const uint32_t stg = sb + (i % STAGES) * STAGE_B;
        const uint32_t sA = stg;
        const uint32_t sW = stg + A_TILE_B;

#pragma unroll
        for (int q = 0; q < 4; q++) {
            const int cc = q * 2 + lchk;
            uint32_t b[4][2], a[2][4];
#pragma unroll
            for (int np = 0; np < 2; np++) {
                uint32_t r0, r1, r2, r3;
                ldsm4(sW + baseW[np] + ((cc ^ xW[np]) << 4), r0, r1, r2, r3);
                b[np * 2][0] = r0; b[np * 2 + 1][0] = r1;
                b[np * 2][1] = r2; b[np * 2 + 1][1] = r3;
            }
#pragma unroll
            for (int mt = 0; mt < 2; mt++)
                ldsm4(sA + baseA[mt] + ((cc ^ xA[mt]) << 4),
                      a[mt][0], a[mt][1], a[mt][2], a[mt][3]);
#pragma unroll
            for (int mt = 0; mt < 2; mt++)
#pragma unroll
                for (int nt = 0; nt < 4; nt++)
                    mma16816(acc[mt][nt], a[mt], b[nt]);
        }
        // no trailing sync: stage reuse is protected by the top barrier
    }

    // ---------------- epilogue ----------------
    const int rbase = bm * BM + wm * 32;
    const int cbase = bn * BN + wn * 32;
    const int qr = lane >> 2;            // 0..7
    const int qc = (lane & 3) * 2;       // 0,2,4,6

    if (mode == 0) {
        // gate-permuted columns: p = j*4 + gate (i,f,g,o). Even lane holds (p,p+1)=(i,f),
        // odd partner holds (p+2,p+3)=(g,o); shfl_xor(1) assembles the quad.
#pragma unroll
        for (int mt = 0; mt < 2; mt++) {
#pragma unroll
            for (int nt = 0; nt < 4; nt++) {
                const int p = cbase + nt * 8 + qc;
                const float bv0 = bias[p], bv1 = bias[p + 1];
                const float v0 = acc[mt][nt][0] + bv0;
                const float v1 = acc[mt][nt][1] + bv1;
                const float v2 = acc[mt][nt][2] + bv0;
                const float v3 = acc[mt][nt][3] + bv1;
                const float x0 = __shfl_xor_sync(0xffffffffu, v0, 1);
                const float x1 = __shfl_xor_sync(0xffffffffu, v1, 1);
                const float x2 = __shfl_xor_sync(0xffffffffu, v2, 1);
                const float x3 = __shfl_xor_sync(0xffffffffu, v3, 1);
                if (!(lane & 1)) {
                    const int j = p >> 2;            // hidden unit
                    const int r0 = rbase + mt * 16 + qr;
#pragma unroll
                    for (int half = 0; half < 2; half++) {
                        const int row = r0 + half * 8;
                        const float iv = half ? v2 : v0;
                        const float fv = half ? v3 : v1;
                        const float gv = half ? x2 : x0;
                        const float ov = half ? x3 : x1;
                        const float cold = first ? 0.0f : cstate[(size_t)row * HDIM + j];
                        const float cn = sigmoidf_(fv) * cold + sigmoidf_(iv) * tanhf(gv);
                        cstate[(size_t)row * HDIM + j] = cn;
                        const float h = sigmoidf_(ov) * tanhf(cn);
                        hw[(size_t)row * HDIM + j] = __float2half(h);
                    }
                }
            }
        }
    } else {
#pragma unroll
        for (int mt = 0; mt < 2; mt++) {
#pragma unroll
            for (int nt = 0; nt < 4; nt++) {
                const int col = cbase + nt * 8 + qc;
                const float bv0 = bias[col], bv1 = bias[col + 1];
#pragma unroll
                for (int half = 0; half < 2; half++) {
                    const int row = rbase + mt * 16 + qr + half * 8;
                    const float v0 = acc[mt][nt][half * 2 + 0] + bv0;
                    const float v1 = acc[mt][nt][half * 2 + 1] + bv1;
                    *(float2*)(Co + (size_t)row * (DSTEPS * FDIM) + col) = make_float2(v0, v1);
                    *(__half2*)(ox + (size_t)row * FDIM + col) =
                        __halves2half2(__float2half(v0), __float2half(v1));
                }
            }
        }
    }
}

// ---------------- elementwise prep kernels ----------------
__global__ void split_act(const float* __restrict__ x, __half* __restrict__ o)
{
    const int idx = blockIdx.x * blockDim.x + threadIdx.x;   // MROWS*FDIM
    o[idx] = __float2half(x[idx]);
}

// gates weights gate-permuted fp16: output row p = j*4 + gate, src row = gate*H + j
__global__ void split_weights(const float* __restrict__ W_ih, const float* __restrict__ W_hh,
                              const float* __restrict__ W_cls,
                              const float* __restrict__ b_ih, const float* __restrict__ b_hh,
                              __half* __restrict__ wg, __half* __restrict__ wc,
                              float* __restrict__ biasg)
{
    const int idx = blockIdx.x * blockDim.x + threadIdx.x;
    const int NG = GDIM * KFUSE;
    if (idx < NG) {
        const int p = idx / KFUSE, col = idx - p * KFUSE;
        const int src_n = (p & 3) * HDIM + (p >> 2);
        const float v = (col < FDIM) ? W_ih[(size_t)src_n * FDIM + col]
                                     : W_hh[(size_t)src_n * HDIM + (col - FDIM)];
        wg[idx] = __float2half(v);
        if (idx < GDIM) {
            const int sn = (idx & 3) * HDIM + (idx >> 2);
            biasg[idx] = b_ih[sn] + b_hh[sn];
        }
    } else {
        const int i2 = idx - NG;                // FDIM*HDIM
        wc[i2] = __float2half(W_cls[i2]);
    }
}

// ---------------- launch ----------------
extern "C" void kernel_launch(void* const* d_in, const int* in_sizes, int n_in,
                              void* d_out, int out_size)
{
    const float* x     = (const float*)d_in[0];
    const float* W_ih  = (const float*)d_in[1];
    const float* W_hh  = (const float*)d_in[2];
    const float* b_ih  = (const float*)d_in[3];
    const float* b_hh  = (const float*)d_in[4];
    const float* W_cls = (const float*)d_in[5];
    const float* b_cls = (const float*)d_in[6];
    float* out = (float*)d_out;                    // [8192 rows, 8 steps, 1024]

    __half *p_o, *p_wg, *p_wc;
    __half *p_h[2];
    float *p_biasg, *p_c;
    cudaGetSymbolAddress((void**)&p_o, g_out);
    {
        __half* base;
        cudaGetSymbolAddress((void**)&base, g_h);
        p_h[0] = base; p_h[1] = base + (size_t)MROWS * HDIM;
    }
    cudaGetSymbolAddress((void**)&p_wg, g_wg);
    cudaGetSymbolAddress((void**)&p_wc, g_wc);
    cudaGetSymbolAddress((void**)&p_biasg, g_biasg);
    cudaGetSymbolAddress((void**)&p_c, g_c);

    cudaFuncSetAttribute(gemm_hmma, cudaFuncAttributeMaxDynamicSharedMemorySize, SMEM_TOTAL);

    split_act<<<(MROWS * FDIM) / 256, 256>>>(x, p_o);
    split_weights<<<(GDIM * KFUSE + FDIM * HDIM) / 256, 256>>>(W_ih, W_hh, W_cls, b_ih, b_hh,
                                                               p_wg, p_wc, p_biasg);

    const dim3 gridG(GDIM / BN, MROWS / BM);   // (32, 64)
    const dim3 gridC(FDIM / BN, MROWS / BM);   // (16, 64)

    for (int d = 0; d < DSTEPS; d++) {
        const int wb = d & 1;                 // h write buffer
        const int rb = (d + 1) & 1;           // h read buffer (prev step)
        // gates GEMM + fused LSTM cell. Step 0: K=1024 (h0 == 0, skip h chunks).
        const int Kg = (d == 0) ? FDIM : KFUSE;
        gemm_hmma<<<gridG, NTHR, SMEM_TOTAL>>>(p_o, FDIM,
                                               p_h[rb], FDIM / BK,
                                               p_wg, KFUSE,
                                               Kg, p_biasg,
                                               p_c, nullptr,
                                               nullptr,
                                               p_h[wb],
                                               0, d == 0 ? 1 : 0);
        // out = h @ W_cls^T + b_cls -> d_out slice d; fp16 copy into out buffer
        gemm_hmma<<<gridC, NTHR, SMEM_TOTAL>>>(p_h[wb], HDIM,
                                               nullptr, 1 << 30,
                                               p_wc, HDIM,
                                               HDIM, b_cls,
                                               nullptr, out + (size_t)d * FDIM,
                                               p_o,
                                               nullptr,
                                               1, 0);
    }
}